// round 16
// baseline (speedup 1.0000x reference)
#include <cuda_runtime.h>

// GRU4Rec user module: ragged GRU(128) -> dense(128) -> L2 normalize.
// Inputs: x f32[T,128], offset i32[B] (i64 auto-detect), W_ih f32[384,128],
//         W_hh f32[384,128], W_dense f32[128,128], b_dense f32[128]
// Output: f32[B,128]
//
// R16: k_rec v6 — half-row split across adjacent lane pairs (768 threads,
// 24 warps, 32 weight regs/thread), shfl_xor(1) half-combine (no smem
// round-trip), interleaved 16B chunks so each wavefront carries 2 distinct
// chunks. NSEQ=2 + counting-sort pairing. k_xproj = proven R7 (800us).

#define DIMD 128
#define DIMH 128
#define G3   384
#define MAXB 4096
#define MAXLEN 200

__device__ float g_xproj[(size_t)2048 * MAXLEN * G3];
__device__ int g_off[MAXB];
__device__ int g_len[MAXB];
__device__ int g_order[MAXB];

__device__ __forceinline__ void ffma2(unsigned long long &acc,
                                      unsigned long long a,
                                      unsigned long long b) {
    asm("fma.rn.f32x2 %0, %1, %2, %0;" : "+l"(acc) : "l"(a), "l"(b));
}
__device__ __forceinline__ float f2lo(unsigned long long v) {
    return __uint_as_float((unsigned int)v);
}
__device__ __forceinline__ float f2hi(unsigned long long v) {
    return __uint_as_float((unsigned int)(v >> 32));
}
__device__ __forceinline__ float rcp_approx(float x) {
    float r;
    asm("rcp.approx.f32 %0, %1;" : "=f"(r) : "f"(x));
    return r;
}
__device__ __forceinline__ float fast_sigmoid(float v) {
    return rcp_approx(1.0f + __expf(-v));
}
__device__ __forceinline__ float fast_tanh(float v) {
    float av = fabsf(v);
    float e = __expf(-2.0f * av);
    float m = (1.0f - e) * rcp_approx(1.0f + e);
    return copysignf(m, v);
}
__device__ __forceinline__ int load_off(const void* p, int i, bool is64) {
    return is64 ? (int)((const long long*)p)[i] : ((const int*)p)[i];
}

// ---------------------------------------------------------------------------
// K0: offsets/lengths + counting sort of sequence indices by length.
// ---------------------------------------------------------------------------
__global__ void k_sort(const void* __restrict__ off_raw, int T, int B) {
    __shared__ int s_cnt[MAXLEN + 1];
    const int tid = threadIdx.x;
    const bool is64 = (B > 1) && (((const int*)off_raw)[1] == 0);

    for (int i = tid; i <= MAXLEN; i += blockDim.x) s_cnt[i] = 0;
    __syncthreads();

    for (int i = tid; i < B; i += blockDim.x) {
        int o  = load_off(off_raw, i, is64);
        int oe = (i + 1 < B) ? load_off(off_raw, i + 1, is64) : T;
        int l = oe - o;
        if (o < 0) o = 0;
        if (l < 0) l = 0;
        if (l > MAXLEN) l = MAXLEN;
        g_off[i] = o;
        g_len[i] = l;
        atomicAdd(&s_cnt[l], 1);
    }
    __syncthreads();

    if (tid == 0) {
        int run = 0;
        for (int j = 0; j <= MAXLEN; j++) { int c = s_cnt[j]; s_cnt[j] = run; run += c; }
    }
    __syncthreads();

    for (int i = tid; i < B; i += blockDim.x) {
        int pos = atomicAdd(&s_cnt[g_len[i]], 1);
        g_order[pos] = i;
    }
}

// ---------------------------------------------------------------------------
// K1: x_proj = x @ W_ih^T. 4-token tiles (exact R7 version, proven 800us).
// ---------------------------------------------------------------------------
__global__ __launch_bounds__(384, 1)
void k_xproj(const float* __restrict__ x,
             const float* __restrict__ W_ih,
             int T, int chunk) {
    const int g = threadIdx.x;

    int t0 = blockIdx.x * chunk;
    int t1 = min(T, t0 + chunk);
    if (t0 >= t1) return;  // uniform across block

    unsigned long long Wr[64];
    {
        const unsigned long long* Wp =
            (const unsigned long long*)(W_ih + (size_t)g * DIMD);
        #pragma unroll
        for (int j = 0; j < 64; j++) Wr[j] = Wp[j];
    }

    __shared__ __align__(16) float sx[2][4][DIMD];

    if (g < 128) {
        int tk = t0 + (g >> 5);
        if (tk < t1)
            ((float4*)sx[0][g >> 5])[g & 31] =
                ((const float4*)x)[(size_t)tk * 32 + (g & 31)];
    }
    __syncthreads();

    int buf = 0;
    for (int ts = t0; ts < t1; ts += 4) {
        if (g < 128) {
            int tk = ts + 4 + (g >> 5);
            if (tk < t1)
                ((float4*)sx[buf ^ 1][g >> 5])[g & 31] =
                    ((const float4*)x)[(size_t)tk * 32 + (g & 31)];
        }

        unsigned long long a0[4], a1[4];
        #pragma unroll
        for (int k = 0; k < 4; k++) { a0[k] = 0ull; a1[k] = 0ull; }

        const ulonglong2* hp0 = (const ulonglong2*)sx[buf][0];
        const ulonglong2* hp1 = (const ulonglong2*)sx[buf][1];
        const ulonglong2* hp2 = (const ulonglong2*)sx[buf][2];
        const ulonglong2* hp3 = (const ulonglong2*)sx[buf][3];
        #pragma unroll
        for (int j = 0; j < 32; j++) {
            ulonglong2 v0 = hp0[j], v1 = hp1[j], v2 = hp2[j], v3 = hp3[j];
            ffma2(a0[0], Wr[2 * j], v0.x);  ffma2(a1[0], Wr[2 * j + 1], v0.y);
            ffma2(a0[1], Wr[2 * j], v1.x);  ffma2(a1[1], Wr[2 * j + 1], v1.y);
            ffma2(a0[2], Wr[2 * j], v2.x);  ffma2(a1[2], Wr[2 * j + 1], v2.y);
            ffma2(a0[3], Wr[2 * j], v3.x);  ffma2(a1[3], Wr[2 * j + 1], v3.y);
        }
        #pragma unroll
        for (int k = 0; k < 4; k++) {
            int tk = ts + k;
            if (tk < t1) {
                float s = (f2lo(a0[k]) + f2hi(a0[k])) + (f2lo(a1[k]) + f2hi(a1[k]));
                g_xproj[(size_t)tk * G3 + g] = s;
            }
        }

        __syncthreads();
        buf ^= 1;
    }
}

// ---------------------------------------------------------------------------
// K2 v6: GRU recurrence, 2 length-sorted sequences per block, 768 threads.
// Thread (r, h): r = tid>>1 (row 0..383), h = tid&1 (half). Thread holds the
// interleaved half of W_hh row r: 16B chunks h, h+2, ..., h+30 (32 ull regs).
// Adjacent lanes (2k, 2k+1) share r; halves combined with one shfl_xor(1).
// Half h streams sequence h's x-projection (one LDG per thread per step).
// ---------------------------------------------------------------------------
__global__ __launch_bounds__(768, 1)
void k_rec(const float* __restrict__ W_hh,
           const float* __restrict__ W_dense,
           const float* __restrict__ b_dense,
           float* __restrict__ out,
           int B) {
    const int tid = threadIdx.x;
    const int h = tid & 1;
    const int r = tid >> 1;              // 0..383

    const int i0 = 2 * blockIdx.x;
    const int seq0 = g_order[i0];
    const int seq1 = (i0 + 1 < B) ? g_order[i0 + 1] : -1;
    const int len0 = g_len[seq0];
    const int len1 = (seq1 >= 0) ? g_len[seq1] : 0;
    const int off0 = g_off[seq0];
    const int off1 = (seq1 >= 0) ? g_off[seq1] : 0;
    const int lmax = max(len0, len1);

    // interleaved half-row weights: chunk k lives at float offset h*4 + 8k
    unsigned long long Wr[32];
    {
        const float* Wp = W_hh + (size_t)r * DIMH + h * 4;
        #pragma unroll
        for (int k = 0; k < 16; k++) {
            Wr[2 * k]     = *(const unsigned long long*)(Wp + 8 * k);
            Wr[2 * k + 1] = *(const unsigned long long*)(Wp + 8 * k + 2);
        }
    }

    __shared__ __align__(16) float sh_h[2][DIMH];
    __shared__ float sh_pre[2][G3];
    __shared__ float sh_xgn[2][DIMH];
    __shared__ float sred[8];
    __shared__ int sh_len[2];

    if (tid < 256) sh_h[tid >> 7][tid & 127] = 0.0f;
    if (tid == 0) { sh_len[0] = len0; sh_len[1] = len1; }
    __syncthreads();

    const int mylen = h ? len1 : len0;
    const int myoff = h ? off1 : off0;
    const float* xg = g_xproj + (size_t)myoff * G3 + r;
    float xv = (0 < mylen) ? xg[0] : 0.0f;

    for (int t = 0; t < lmax; t++) {
        float xn = (t + 1 < mylen) ? xg[(size_t)(t + 1) * G3] : 0.0f;

        unsigned long long a00 = 0ull, a01 = 0ull, a10 = 0ull, a11 = 0ull;
        const ulonglong2* hp0 = ((const ulonglong2*)sh_h[0]) + h;
        const ulonglong2* hp1 = ((const ulonglong2*)sh_h[1]) + h;
        #pragma unroll
        for (int k = 0; k < 16; k++) {
            ulonglong2 v0 = hp0[2 * k];      // lane pair reads 2 distinct chunks
            ulonglong2 v1 = hp1[2 * k];
            ffma2(a00, Wr[2 * k],     v0.x);
            ffma2(a01, Wr[2 * k + 1], v0.y);
            ffma2(a10, Wr[2 * k],     v1.x);
            ffma2(a11, Wr[2 * k + 1], v1.y);
        }
        float d0 = (f2lo(a00) + f2hi(a00)) + (f2lo(a01) + f2hi(a01));
        float d1 = (f2lo(a10) + f2hi(a10)) + (f2lo(a11) + f2hi(a11));
        // combine halves across the lane pair (both lanes get full sums)
        d0 += __shfl_xor_sync(0xffffffffu, d0, 1);
        d1 += __shfl_xor_sync(0xffffffffu, d1, 1);

        // half h publishes sequence h's row r
        float dm = h ? d1 : d0;
        if (r < 2 * DIMH) {
            sh_pre[h][r] = dm + xv;          // r,z pre-activations
        } else {
            sh_pre[h][r] = dm;               // n: hg separate (r scales hg)
            sh_xgn[h][r - 2 * DIMH] = xv;
        }
        __syncthreads();

        if (tid < 256) {                     // gates: s = tid>>7, j = tid&127
            int s = tid >> 7;
            int j = tid & 127;
            if (t < sh_len[s]) {
                float rg = fast_sigmoid(sh_pre[s][j]);
                float zg = fast_sigmoid(sh_pre[s][DIMH + j]);
                float n  = fast_tanh(fmaf(rg, sh_pre[s][2 * DIMH + j], sh_xgn[s][j]));
                float ho = sh_h[s][j];
                sh_h[s][j] = fmaf(zg, ho - n, n);
            }
        }
        __syncthreads();

        xv = xn;
    }

    // dense + L2 normalize: threads 0..255 (s = tid>>7, d = tid&127)
    const int s1 = tid >> 7;
    const int d1 = tid & 127;
    float val = 0.0f;
    if (tid < 256) {
        unsigned long long a0 = 0ull, a1 = 0ull;
        const unsigned long long* Wd =
            (const unsigned long long*)(W_dense + (size_t)d1 * DIMH);
        const ulonglong2* hp = (const ulonglong2*)sh_h[s1];
        #pragma unroll
        for (int j = 0; j < 32; j++) {
            ulonglong2 hv = hp[j];
            ffma2(a0, Wd[2 * j],     hv.x);
            ffma2(a1, Wd[2 * j + 1], hv.y);
        }
        val = (f2lo(a0) + f2hi(a0)) + (f2lo(a1) + f2hi(a1)) + b_dense[d1];

        float ss = val * val;
        #pragma unroll
        for (int sh = 16; sh > 0; sh >>= 1)
            ss += __shfl_xor_sync(0xffffffffu, ss, sh);
        if ((tid & 31) == 0) sred[tid >> 5] = ss;
    }
    __syncthreads();

    if (tid < 256) {
        int b4 = s1 * 4;
        float ss = sred[b4] + sred[b4 + 1] + sred[b4 + 2] + sred[b4 + 3];
        float nrm = fmaxf(sqrtf(ss), 1e-12f);
        int sq = s1 ? seq1 : seq0;
        if (sq >= 0)
            out[(size_t)sq * DIMD + d1] = val / nrm;
    }
}

// ---------------------------------------------------------------------------
extern "C" void kernel_launch(void* const* d_in, const int* in_sizes, int n_in,
                              void* d_out, int out_size) {
    const float* x       = (const float*)d_in[0];
    const void*  off     = d_in[1];                   // int32 or int64
    const float* W_ih    = (const float*)d_in[2];
    const float* W_hh    = (const float*)d_in[3];
    const float* W_dense = (const float*)d_in[4];
    const float* b_dense = (const float*)d_in[5];
    float*       out     = (float*)d_out;

    const int T = in_sizes[0] / DIMD;   // total tokens
    const int B = out_size / DIMD;      // number of sequences

    const int G1 = 1184;                // 8 waves at 1 block/SM on 148 SMs
    const int chunk = (T + G1 - 1) / G1;
    k_xproj<<<G1, 384>>>(x, W_ih, T, chunk);

    k_sort<<<1, 256>>>(off, T, B);

    const int G2 = (B + 1) / 2;
    k_rec<<<G2, 768>>>(W_hh, W_dense, b_dense, out, B);
}